// round 6
// baseline (speedup 1.0000x reference)
#include <cuda_runtime.h>
#include <math.h>

#define D_    1024
#define E_    8
#define B_    64
#define S_    1024
#define NTOK  65536
#define NB2   1024                 // K2 blocks: 64 tokens each, batch-aligned (16 blocks/batch)
#define MASK_N   (B_*S_*E_)        // 524288
#define IDX_OFF  MASK_N
#define LOSS_OFF (MASK_N + B_*2)   // 524416
#define SCALE 0.03125f             // D^-0.5

typedef unsigned long long u64;

// ----- static scratch (no allocation) -----
__device__ float g_Mpart[32*8192];   // 1 MB: o-tile partials of M, [tile][e*1024+d]
__device__ float g_M[8192];          // M[e][d]
__device__ float g_c[8];
__device__ float g_pws[NB2*8];       // per-block softmax sums per expert
__device__ float g_paux[NB2];        // per-block aux partial

__device__ __forceinline__ void ffma2(u64 &d, u64 a, u64 b){
    asm("fma.rn.f32x2 %0, %1, %2, %0;" : "+l"(d) : "l"(a), "l"(b));
}
__device__ __forceinline__ float2 unpack2(u64 v){
    float2 r; asm("mov.b64 {%0,%1}, %2;" : "=f"(r.x), "=f"(r.y) : "l"(v)); return r;
}
union F4u { float4 f; u64 u[2]; };

// ================= K1: partial M[d,e] = sum_o Wq[o,d]*key[e,o] over 32-wide o-tile =========
__global__ void k1(const float* __restrict__ Wq, const float* __restrict__ key){
    __shared__ float sk[256];                  // key[e][o-tile], 8 x 32
    int tid = threadIdx.x;
    int ot = blockIdx.x & 31, dt = blockIdx.x >> 5;
    int o0 = ot << 5;
    {
        int e = tid >> 5, oo = tid & 31;
        sk[tid] = key[(e<<10) + o0 + oo];
    }
    __syncthreads();
    int d = (dt<<8) + tid;
    float acc[8] = {0.f,0.f,0.f,0.f,0.f,0.f,0.f,0.f};
    #pragma unroll 8
    for (int oo = 0; oo < 32; oo++){
        float w = Wq[(size_t)(o0+oo)*D_ + d];  // coalesced in d
        #pragma unroll
        for (int e = 0; e < 8; e++) acc[e] = fmaf(w, sk[(e<<5)+oo], acc[e]);
    }
    #pragma unroll
    for (int e = 0; e < 8; e++)
        g_Mpart[ot*8192 + (e<<10) + d] = acc[e];
}

// ================= K1b: reduce 32 partials -> g_M; compute c[e] = key[e]·bq =================
__global__ void k1b(const float* __restrict__ key, const float* __restrict__ bq){
    int i = blockIdx.x*256 + threadIdx.x;      // 0..8191  (= e*1024+d)
    float t = 0.f;
    #pragma unroll
    for (int k = 0; k < 32; k++) t += g_Mpart[k*8192 + i];
    g_M[i] = t;

    if (blockIdx.x == 0){
        int e = threadIdx.x >> 5, lane = threadIdx.x & 31;
        float c = 0.f;
        for (int o = lane; o < D_; o += 32) c = fmaf(key[(e<<10)+o], bq[o], c);
        #pragma unroll
        for (int off = 16; off > 0; off >>= 1)
            c += __shfl_xor_sync(0xffffffffu, c, off);
        if (lane == 0) g_c[e] = c;
    }
}

// ================= K2: fused projection + softmax + per-block partial sums =================
// 512 threads = 16 warps; each warp handles 4 tokens with 8 lanes per token.
// M is read via __ldg (L1 const path): per warp-LDG the 8 distinct 16B addrs x4 broadcast
// touch ONE 128B line -> 1 L1 wavefront (vs 4 smem phases). M (32KB) stays L1-resident.
__global__ void __launch_bounds__(512,2) k2(const float* __restrict__ x){
    __shared__ float sRed[16][12];
    int tid = threadIdx.x;
    int lane = tid & 31, warp = tid >> 5;
    int g = lane >> 3, s8 = lane & 7;
    int token = blockIdx.x*64 + warp*4 + g;
    const float4* xr = (const float4*)(x + (size_t)token*D_);
    const ulonglong2* M2 = (const ulonglong2*)g_M;   // 4 floats per entry

    u64 acc[8];
    #pragma unroll
    for (int e = 0; e < 8; e++) acc[e] = 0ULL;

    // chunk = 32 d's: 8 lanes x float4. x LDG.128 = 4 rows x 128B (4 lines, all sectors used).
    #pragma unroll 4
    for (int ch = 0; ch < 32; ch++){
        F4u xv; xv.f = __ldcs(&xr[ch*8 + s8]);   // streamed, no reuse
        int idx = ((ch<<5) + (s8<<2)) >> 2;      // ulonglong2 index within a 1024-d row
        #pragma unroll
        for (int e = 0; e < 8; e++){
            ulonglong2 mv = __ldg(&M2[(e<<8) + idx]);
            ffma2(acc[e], xv.u[0], mv.x);
            ffma2(acc[e], xv.u[1], mv.y);
        }
    }

    // collapse pairs + reduce over the 8 lanes of this token
    float s[8];
    #pragma unroll
    for (int e = 0; e < 8; e++){
        float2 p = unpack2(acc[e]);
        float v = p.x + p.y;
        #pragma unroll
        for (int off = 1; off < 8; off <<= 1)
            v += __shfl_xor_sync(0xffffffffu, v, off);
        s[e] = (v + __ldg(&g_c[e])) * SCALE;
    }

    // softmax (8 lanes of a token hold identical s[] -> redundant but cheap)
    float mx = s[0];
    #pragma unroll
    for (int e = 1; e < 8; e++) mx = fmaxf(mx, s[e]);
    float w[8], sum = 0.f;
    #pragma unroll
    for (int e = 0; e < 8; e++){ w[e] = __expf(s[e] - mx); sum += w[e]; }
    float inv = 1.0f / sum;
    float aux = 0.f;
    #pragma unroll
    for (int e = 0; e < 8; e++){ w[e] *= inv; aux += w[e] * __logf(w[e] + 1e-9f); }

    // count each token once: zero non-lead lanes, then full-warp butterfly
    float lead = (s8 == 0) ? 1.f : 0.f;
    aux *= lead;
    #pragma unroll
    for (int e = 0; e < 8; e++) w[e] *= lead;
    #pragma unroll
    for (int off = 16; off > 0; off >>= 1){
        #pragma unroll
        for (int e = 0; e < 8; e++) w[e] += __shfl_xor_sync(0xffffffffu, w[e], off);
        aux += __shfl_xor_sync(0xffffffffu, aux, off);
    }
    if (lane == 0){
        #pragma unroll
        for (int e = 0; e < 8; e++) sRed[warp][e] = w[e];
        sRed[warp][8] = aux;
    }
    __syncthreads();
    if (tid < 9){
        float t = 0.f;
        #pragma unroll
        for (int wp = 0; wp < 16; wp++) t += sRed[wp][tid];
        if (tid < 8) g_pws[blockIdx.x*8 + tid] = t;
        else         g_paux[blockIdx.x]        = t;
    }
}

// ================= K4: mask write + top-2 + indices + loss (k3 fused in) =================
// 256 blocks x 256 threads. Block blk covers batch b=blk>>2, quarter q=blk&3 (256 tokens).
// Each block recomputes its batch's top-2 from g_pws (cheap, deterministic).
// q==0 blocks write indices for their batch. Block 0 additionally computes the loss.
__global__ void __launch_bounds__(256) k4(float* __restrict__ out, int out_size){
    __shared__ float ssc[8];
    __shared__ float smask[8];
    __shared__ float sm2b[64][8];   // block 0 only
    __shared__ float sauxw[8];      // block 0 only
    __shared__ float scnt[8];       // block 0 only
    int blk = blockIdx.x, tid = threadIdx.x;
    int b = blk >> 2, q = blk & 3;

    // scores for this block's batch: 8 threads, 16 loads each (vectorizable float4 pairs)
    if (tid < 8){
        float sc = 0.f;
        #pragma unroll
        for (int j = 0; j < 16; j++) sc += g_pws[((b<<4)+j)*8 + tid];
        ssc[tid] = sc;
    }
    __syncthreads();
    if (tid == 0){
        int i1 = 0; float v1 = ssc[0];
        #pragma unroll
        for (int e = 1; e < 8; e++) if (ssc[e] > v1){ v1 = ssc[e]; i1 = e; }
        int i2 = -1; float v2 = -3.0e38f;
        #pragma unroll
        for (int e = 0; e < 8; e++) if (e != i1 && ssc[e] > v2){ v2 = ssc[e]; i2 = e; }
        #pragma unroll
        for (int e = 0; e < 8; e++)
            smask[e] = (e == i1 || e == i2) ? 1.f : 0.f;
        if (q == 0 && out_size > IDX_OFF + b*2 + 1){
            out[IDX_OFF + b*2 + 0] = (float)i1;
            out[IDX_OFF + b*2 + 1] = (float)i2;
        }
    }
    __syncthreads();

    // write 256 tokens x 8 floats
    {
        float4 a0 = make_float4(smask[0], smask[1], smask[2], smask[3]);
        float4 a1 = make_float4(smask[4], smask[5], smask[6], smask[7]);
        int t = (b << 10) + (q << 8) + tid;
        float4* o = (float4*)out;
        o[t*2 + 0] = a0;
        o[t*2 + 1] = a1;
    }

    // ---- block 0: router loss ----
    if (blk == 0){
        int lane = tid & 31, warp = tid >> 5;
        // aux over 1024 partials
        float a = g_paux[tid] + g_paux[tid+256] + g_paux[tid+512] + g_paux[tid+768];
        #pragma unroll
        for (int off = 16; off > 0; off >>= 1)
            a += __shfl_xor_sync(0xffffffffu, a, off);
        if (lane == 0) sauxw[warp] = a;

        // all-batch top-2 -> mask2d rows
        if (tid < 64){
            int bb = tid;
            float sc[8];
            #pragma unroll
            for (int e = 0; e < 8; e++){
                float t = 0.f;
                #pragma unroll
                for (int j = 0; j < 16; j++) t += g_pws[((bb<<4)+j)*8 + e];
                sc[e] = t;
            }
            int i1 = 0; float v1 = sc[0];
            #pragma unroll
            for (int e = 1; e < 8; e++) if (sc[e] > v1){ v1 = sc[e]; i1 = e; }
            int i2 = -1; float v2 = -3.0e38f;
            #pragma unroll
            for (int e = 0; e < 8; e++) if (e != i1 && sc[e] > v2){ v2 = sc[e]; i2 = e; }
            #pragma unroll
            for (int e = 0; e < 8; e++)
                sm2b[bb][e] = (e == i1 || e == i2) ? 1.f : 0.f;
        }
        __syncthreads();
        if (tid < 8){
            float c = 0.f;
            #pragma unroll
            for (int bb = 0; bb < 64; bb++) c += sm2b[bb][tid];
            scnt[tid] = c;
        }
        __syncthreads();
        if (tid == 0){
            float auxtot = 0.f;
            #pragma unroll
            for (int wp = 0; wp < 8; wp++) auxtot += sauxw[wp];
            float kl = 0.f;
            const float ip = 0.125f;
            const float lip = logf(0.125f);
            #pragma unroll
            for (int e = 0; e < 8; e++){
                float usage = scnt[e] * (1.0f/64.0f);   // mask2d.sum(0) * S/(B*S)
                kl += ip * (lip - logf(usage));
            }
            kl *= 0.125f;                               // batchmean over E
            float auxm = auxtot * (1.0f / (float)(B_*S_*E_));
            if (out_size > LOSS_OFF)
                out[LOSS_OFF] = 1e-3f*kl + 1e-3f*auxm;
        }
    }
}

extern "C" void kernel_launch(void* const* d_in, const int* in_sizes, int n_in,
                              void* d_out, int out_size){
    (void)in_sizes; (void)n_in;
    const float* x   = (const float*)d_in[0];
    const float* Wq  = (const float*)d_in[1];
    const float* bq  = (const float*)d_in[2];
    const float* key = (const float*)d_in[3];
    float* out = (float*)d_out;

    k1 <<<128,  256>>>(Wq, key);
    k1b<<<32,   256>>>(key, bq);
    k2 <<<NB2,  512>>>(x);
    k4 <<<256,  256>>>(out, out_size);
}